// round 9
// baseline (speedup 1.0000x reference)
#include <cuda_runtime.h>
#include <math.h>
#include <stdint.h>

// ---------------------------------------------------------------------------
//   N = 4096, DIM_IN = 256, DIM_H = 128, DIM_OUT = 128
//   Xs = relu((A_s@X_s)@W1); Xs = relu((A_s@Xs)@W2)   (same for t)
//   S  = exp((Xs@W3)@Xt^T)
//   out_s = (S@Xs)@W4 ; out_t = (S@Xt)@W4
// Output: [out_s | out_t | S]
// NOTE: tcgen05 is NOT available — harness compiles PTX to .target sm_103
// (no 'a' suffix); arch-specific instructions fail ptxas. HMMA mma.sync only.
// ---------------------------------------------------------------------------

#define GN    4096
#define DIN   256
#define DH    128

__device__ float g_split[4u * 4096u * 256u];   // split-K partials
__device__ float g_bufAX[4096 * 256];          // A@X intermediate / XsXt pack
__device__ float g_bufH [4096 * 128];
__device__ float g_Xs   [4096 * 128];
__device__ float g_Xt   [4096 * 128];
__device__ float g_Q    [4096 * 128];
__device__ float g_P    [8192 * 128];          // [Ps; Pt] stacked

// ---------------------------------------------------------------------------
// helpers
// ---------------------------------------------------------------------------
__device__ __forceinline__ uint32_t f2tf32(float x) {
    uint32_t r;
    asm("cvt.rna.tf32.f32 %0, %1;" : "=r"(r) : "f"(x));
    return r;
}

__device__ __forceinline__ void mma_tf32(float* c, const uint32_t* a, const uint32_t* b) {
    asm volatile(
        "mma.sync.aligned.m16n8k8.row.col.f32.tf32.tf32.f32 "
        "{%0,%1,%2,%3}, {%4,%5,%6,%7}, {%8,%9}, {%0,%1,%2,%3};\n"
        : "+f"(c[0]), "+f"(c[1]), "+f"(c[2]), "+f"(c[3])
        : "r"(a[0]), "r"(a[1]), "r"(a[2]), "r"(a[3]),
          "r"(b[0]), "r"(b[1]));
}

// FFMA-only exp: avoids the MUFU pipe entirely (16.7M exps would otherwise be
// MUFU-throughput-bound at ~125us chip-wide). Inputs are bounded by problem
// construction (no overflow per reference), |t| << 2^22 so the magic-round is
// exact; poly trunc error ~1e-7 over r in [-0.5,0.5].
__device__ __forceinline__ float fast_exp(float x) {
    const float LOG2E = 1.4426950408889634f;
    float t  = x * LOG2E;
    float kf = t + 12582912.0f;                 // 2^23 + 2^22: round-to-nearest-int
    int   k  = __float_as_int(kf) - 0x4B400000; // integer part
    float r  = t - (kf - 12582912.0f);          // r in [-0.5, 0.5]
    // 2^r Taylor, degree 6
    float p = 1.5403530e-4f;
    p = fmaf(p, r, 1.3333558e-3f);
    p = fmaf(p, r, 9.6181291e-3f);
    p = fmaf(p, r, 5.5504109e-2f);
    p = fmaf(p, r, 2.4022651e-1f);
    p = fmaf(p, r, 6.9314718e-1f);
    p = fmaf(p, r, 1.0f);
    return __int_as_float(__float_as_int(p) + (k << 23));
}

// ---------------------------------------------------------------------------
// tf32 tensor-core GEMM, fragment-packed smem, double buffered.
//   C[M,N] = A[M,K] @ B   (TRANSB=false: B [K,N] row-major; true: B [N,K] -> A@B^T)
// CTA tile 128x128x32, 512 threads = 16 warps (4M x 4N), warp tile 32x32.
// Packed A smem: [ks(4)][rb(8)][lane(32)][slot(4)] words, +4 pad per ks plane.
// Packed B smem: [ks(4)][nb(16)][lane(32)*2+slot(2)] with nb stride 66 words.
// gridDim.z > 1 => split-K partials at C + z*M*N (epi must be 0).
// epi: 0 none, 1 relu, 2 exp
// ---------------------------------------------------------------------------
constexpr int A_WORDS = 4 * (8 * 32 * 4 + 4);   // 4*1028 = 4112
constexpr int B_WORDS = 4 * (16 * 66);          // 4*1056 = 4224
constexpr int SMEM_BYTES = (2 * A_WORDS + 2 * B_WORDS) * 4;  // 66,688 B

template <bool TRANSB>
__global__ void __launch_bounds__(512, 1)
mma_gemm(const float* __restrict__ A, const float* __restrict__ B,
         float* __restrict__ C,
         int M, int N, int K, int lda, int ldb, int ldc,
         int kChunk, int epi)
{
    constexpr int BM = 128, BN = 128, BK = 32;
    constexpr int THREADS = 512;
    constexpr int KV = BK / 4;                      // 8
    constexpr int A_LOADS = (BM * KV) / THREADS;    // 2
    constexpr int B_LOADS = (BN * KV) / THREADS;    // 2

    extern __shared__ uint32_t sm[];
    uint32_t* AsBase = sm;                  // [2][A_WORDS]
    uint32_t* BsBase = sm + 2 * A_WORDS;    // [2][B_WORDS]

    const int tid  = threadIdx.x;
    const int lane = tid & 31;
    const int wid  = tid >> 5;
    const int wm   = wid & 3;               // 4 warps along M
    const int wn   = wid >> 2;              // 4 warps along N

    const int mBlock = blockIdx.y * BM;
    const int nBlock = blockIdx.x * BN;
    const int k0     = blockIdx.z * kChunk;

    if (gridDim.z > 1)
        C += (size_t)blockIdx.z * (size_t)M * (size_t)N;

    float4 pa[A_LOADS], pb[B_LOADS];

    float acc[2][4][4];
#pragma unroll
    for (int i = 0; i < 2; i++)
#pragma unroll
        for (int j = 0; j < 4; j++)
#pragma unroll
            for (int r = 0; r < 4; r++) acc[i][j][r] = 0.f;

    auto loadTiles = [&](int kt) {
#pragma unroll
        for (int i = 0; i < A_LOADS; i++) {
            int idx = tid + i * THREADS;
            int r   = idx >> 3;
            int kc  = (idx & 7) * 4;
            pa[i] = *reinterpret_cast<const float4*>(
                        &A[(size_t)(mBlock + r) * lda + kt + kc]);
        }
#pragma unroll
        for (int i = 0; i < B_LOADS; i++) {
            int idx = tid + i * THREADS;
            if constexpr (!TRANSB) {
                int k  = idx >> 5;
                int nc = (idx & 31) * 4;
                pb[i] = *reinterpret_cast<const float4*>(
                            &B[(size_t)(kt + k) * ldb + nBlock + nc]);
            } else {
                int n  = idx >> 3;
                int kc = (idx & 7) * 4;
                pb[i] = *reinterpret_cast<const float4*>(
                            &B[(size_t)(nBlock + n) * ldb + kt + kc]);
            }
        }
    };

    auto storeTiles = [&](int buf) {
        uint32_t* As = AsBase + buf * A_WORDS;
        uint32_t* Bs = BsBase + buf * B_WORDS;
#pragma unroll
        for (int i = 0; i < A_LOADS; i++) {
            int idx = tid + i * THREADS;
            int R   = idx >> 3;
            int kc  = (idx & 7) * 4;
            int ks   = kc >> 3;
            int shi  = (kc >> 2) & 1;
            int rb   = R >> 4;
            int slot = shi * 2 + ((R >> 3) & 1);
            int lb   = (R & 7) * 4;
            uint32_t* p = As + ks * 1028 + rb * 128 + slot;
            p[(lb + 0) * 4] = f2tf32(pa[i].x);
            p[(lb + 1) * 4] = f2tf32(pa[i].y);
            p[(lb + 2) * 4] = f2tf32(pa[i].z);
            p[(lb + 3) * 4] = f2tf32(pa[i].w);
        }
#pragma unroll
        for (int i = 0; i < B_LOADS; i++) {
            int idx = tid + i * THREADS;
            if constexpr (!TRANSB) {
                int k  = idx >> 5;
                int nc = (idx & 31) * 4;
                int ks   = k >> 3;
                int tt   = k & 7;
                int slot = tt >> 2;
                int t    = tt & 3;
                int nb   = nc >> 3;
                int g0   = nc & 7;              // 0 or 4
                uint32_t* p = Bs + ks * 1056 + nb * 66 + slot;
                p[((g0 + 0) * 4 + t) * 2] = f2tf32(pb[i].x);
                p[((g0 + 1) * 4 + t) * 2] = f2tf32(pb[i].y);
                p[((g0 + 2) * 4 + t) * 2] = f2tf32(pb[i].z);
                p[((g0 + 3) * 4 + t) * 2] = f2tf32(pb[i].w);
            } else {
                int n  = idx >> 3;
                int kc = (idx & 7) * 4;
                int ks   = kc >> 3;
                int slot = (kc >> 2) & 1;
                int nb   = n >> 3;
                int g    = n & 7;
                uint32_t* p = Bs + ks * 1056 + nb * 66 + slot;
                p[(g * 4 + 0) * 2] = f2tf32(pb[i].x);
                p[(g * 4 + 1) * 2] = f2tf32(pb[i].y);
                p[(g * 4 + 2) * 2] = f2tf32(pb[i].z);
                p[(g * 4 + 3) * 2] = f2tf32(pb[i].w);
            }
        }
    };

    auto computeTile = [&](int buf) {
        const uint32_t* As = AsBase + buf * A_WORDS;
        const uint32_t* Bs = BsBase + buf * B_WORDS;
#pragma unroll
        for (int ks = 0; ks < 4; ks++) {
            uint32_t af[2][4], bf[4][2];
#pragma unroll
            for (int mt = 0; mt < 2; mt++) {
                uint4 v = *reinterpret_cast<const uint4*>(
                    As + ks * 1028 + (wm * 2 + mt) * 128 + lane * 4);
                af[mt][0] = v.x; af[mt][1] = v.y; af[mt][2] = v.z; af[mt][3] = v.w;
            }
#pragma unroll
            for (int nt = 0; nt < 4; nt++) {
                uint2 v = *reinterpret_cast<const uint2*>(
                    Bs + ks * 1056 + (wn * 4 + nt) * 66 + lane * 2);
                bf[nt][0] = v.x; bf[nt][1] = v.y;
            }
#pragma unroll
            for (int mt = 0; mt < 2; mt++)
#pragma unroll
                for (int nt = 0; nt < 4; nt++)
                    mma_tf32(acc[mt][nt], af[mt], bf[nt]);
        }
    };

    const int kEnd = k0 + kChunk;
    loadTiles(k0);
    storeTiles(0);
    __syncthreads();
    int buf = 0;
    for (int kt = k0; kt < kEnd; kt += BK) {
        bool last = (kt + BK >= kEnd);
        if (!last) loadTiles(kt + BK);
        computeTile(buf);
        if (!last) {
            storeTiles(buf ^ 1);
            __syncthreads();
            buf ^= 1;
        }
    }

    const int g = lane >> 2;
    const int t = lane & 3;
#pragma unroll
    for (int mt = 0; mt < 2; mt++) {
#pragma unroll
        for (int nt = 0; nt < 4; nt++) {
            int r0 = mBlock + wm * 32 + mt * 16 + g;
            int c0 = nBlock + wn * 32 + nt * 8 + 2 * t;
            float2 v0 = make_float2(acc[mt][nt][0], acc[mt][nt][1]);
            float2 v1 = make_float2(acc[mt][nt][2], acc[mt][nt][3]);
            if (epi == 1) {
                v0.x = fmaxf(v0.x, 0.f); v0.y = fmaxf(v0.y, 0.f);
                v1.x = fmaxf(v1.x, 0.f); v1.y = fmaxf(v1.y, 0.f);
            } else if (epi == 2) {
                v0.x = fast_exp(v0.x); v0.y = fast_exp(v0.y);
                v1.x = fast_exp(v1.x); v1.y = fast_exp(v1.y);
            }
            *reinterpret_cast<float2*>(&C[(size_t)r0 * ldc + c0]) = v0;
            *reinterpret_cast<float2*>(&C[(size_t)(r0 + 8) * ldc + c0]) = v1;
        }
    }
}

// Split-K reduction (deterministic order).
__global__ void reduce_kernel(const float* __restrict__ part, float* __restrict__ out,
                              int MN, int splits)
{
    int i = (blockIdx.x * blockDim.x + threadIdx.x) * 4;
    if (i >= MN) return;
    float4 s = *reinterpret_cast<const float4*>(&part[i]);
    for (int z = 1; z < splits; z++) {
        float4 t = *reinterpret_cast<const float4*>(&part[(size_t)z * MN + i]);
        s.x += t.x; s.y += t.y; s.z += t.z; s.w += t.w;
    }
    *reinterpret_cast<float4*>(&out[i]) = s;
}

// Split-K reduce + de-interleave: part [z][4096][256] -> out [8192][128]
__global__ void reduce_deint_kernel(const float* __restrict__ part, float* __restrict__ out,
                                    int splits)
{
    int o = (blockIdx.x * blockDim.x + threadIdx.x) * 4;   // over 8192*128
    int r = o >> 7;
    int c = o & 127;
    size_t src = (size_t)(r & 4095) * 256 + ((r >> 12) << 7) + c;
    const int MN = 4096 * 256;
    float4 s = *reinterpret_cast<const float4*>(&part[src]);
    for (int z = 1; z < splits; z++) {
        float4 t = *reinterpret_cast<const float4*>(&part[(size_t)z * MN + src]);
        s.x += t.x; s.y += t.y; s.z += t.z; s.w += t.w;
    }
    *reinterpret_cast<float4*>(&out[o]) = s;
}

// Pack [Xs | Xt] -> out [4096][256]
__global__ void pack_kernel(const float* __restrict__ Xs, const float* __restrict__ Xt,
                            float* __restrict__ out)
{
    int o = (blockIdx.x * blockDim.x + threadIdx.x) * 4;   // over 4096*256
    int r = o >> 8;
    int c = o & 255;
    float4 v = (c < 128)
        ? *reinterpret_cast<const float4*>(&Xs[(size_t)r * 128 + c])
        : *reinterpret_cast<const float4*>(&Xt[(size_t)r * 128 + (c - 128)]);
    *reinterpret_cast<float4*>(&out[o]) = v;
}

// ---------------------------------------------------------------------------
// Launch helpers
// ---------------------------------------------------------------------------
template <bool TB>
static void mma_launch(const float* A, const float* B, float* C,
                       int M, int N, int K, int lda, int ldb, int ldc,
                       int splits, int epi)
{
    cudaFuncSetAttribute(mma_gemm<TB>, cudaFuncAttributeMaxDynamicSharedMemorySize,
                         SMEM_BYTES);
    dim3 grid(N / 128, M / 128, splits);
    mma_gemm<TB><<<grid, 512, SMEM_BYTES>>>(A, B, C, M, N, K, lda, ldb, ldc,
                                            K / splits, epi);
}

static void reduce_launch(const float* part, float* out, int MN, int splits)
{
    reduce_kernel<<<MN / (4 * 256), 256>>>(part, out, MN, splits);
}

// One GCN branch: Xout = relu((A @ relu((A@X)@W1)) @ W2)
static void gcn_branch(const float* A, const float* X,
                       const float* W1, const float* W2,
                       float* Xout, float* split, float* bufAX, float* bufH)
{
    mma_launch<false>(A, X, split, GN, DIN, GN, GN, DIN, DIN, 2, 0);
    reduce_launch(split, bufAX, GN * DIN, 2);
    mma_launch<false>(bufAX, W1, bufH, GN, DH, DIN, DIN, DH, DH, 1, 1);
    mma_launch<false>(A, bufH, split, GN, DH, GN, GN, DH, DH, 4, 0);
    reduce_launch(split, bufAX, GN * DH, 4);
    mma_launch<false>(bufAX, W2, Xout, GN, DH, DH, DH, DH, DH, 1, 1);
}

extern "C" void kernel_launch(void* const* d_in, const int* in_sizes, int n_in,
                              void* d_out, int out_size)
{
    const float* A_s = (const float*)d_in[0];
    const float* X_s = (const float*)d_in[1];
    const float* A_t = (const float*)d_in[2];
    const float* X_t = (const float*)d_in[3];
    const float* W1  = (const float*)d_in[4];
    const float* W2  = (const float*)d_in[5];
    const float* W3  = (const float*)d_in[6];
    const float* W4  = (const float*)d_in[7];

    float* out_st = (float*)d_out;                       // [8192, 128] = out_s|out_t
    float* S      = out_st + (size_t)2 * GN * DH;        // [4096, 4096]

    float *split, *bufAX, *bufH, *bXs, *bXt, *bQ, *bP;
    cudaGetSymbolAddress((void**)&split, g_split);
    cudaGetSymbolAddress((void**)&bufAX, g_bufAX);
    cudaGetSymbolAddress((void**)&bufH,  g_bufH);
    cudaGetSymbolAddress((void**)&bXs,   g_Xs);
    cudaGetSymbolAddress((void**)&bXt,   g_Xt);
    cudaGetSymbolAddress((void**)&bQ,    g_Q);
    cudaGetSymbolAddress((void**)&bP,    g_P);

    // GCN branches
    gcn_branch(A_s, X_s, W1, W2, bXs, split, bufAX, bufH);
    gcn_branch(A_t, X_t, W1, W2, bXt, split, bufAX, bufH);

    // Q = Xs @ W3
    mma_launch<false>(bXs, W3, bQ, GN, DH, DH, DH, DH, DH, 1, 0);

    // S = exp(Q @ Xt^T)  (written straight into output; FFMA fast_exp epilogue)
    mma_launch<true>(bQ, bXt, S, GN, GN, DH, DH, DH, GN, 1, 2);

    // XsXt = [Xs | Xt]  [4096, 256]  (reuse bufAX)
    pack_kernel<<<GN * 256 / (4 * 256), 256>>>(bXs, bXt, bufAX);

    // P_pair = S @ [Xs|Xt]  [4096,256], K=4096, split-K=4 (one pass over S)
    mma_launch<false>(S, bufAX, split, GN, 2 * DH, GN, GN, 2 * DH, 2 * DH, 4, 0);
    reduce_deint_kernel<<<8192 * 128 / (4 * 256), 256>>>(split, bP, 4);

    // [out_s; out_t] = [Ps; Pt] @ W4   (M = 8192, writes d_out directly)
    mma_launch<false>(bP, W4, out_st, 2 * GN, DH, DH, DH, DH, DH, 1, 0);
}

// round 10
// speedup vs baseline: 1.0049x; 1.0049x over previous
#include <cuda_runtime.h>
#include <math.h>
#include <stdint.h>

// ---------------------------------------------------------------------------
//   N = 4096, DIM_IN = 256, DIM_H = 128, DIM_OUT = 128
//   Xs = relu((A_s@X_s)@W1); Xs = relu((A_s@Xs)@W2)   (same for t)
//   S  = exp((Xs@W3)@Xt^T)
//   out_s = (S@Xs)@W4 ; out_t = (S@Xt)@W4
// Output: [out_s | out_t | S]
// NOTE: tcgen05 is NOT available — harness compiles PTX to .target sm_103
// (no 'a' suffix); arch-specific instructions fail ptxas. HMMA mma.sync only.
// ---------------------------------------------------------------------------

#define GN    4096
#define DIN   256
#define DH    128

__device__ float g_split[4u * 4096u * 256u];   // split-K partials
__device__ float g_bufAX[4096 * 256];          // A@X intermediate / XsXt pack
__device__ float g_bufH [4096 * 128];
__device__ float g_Xs   [4096 * 128];
__device__ float g_Xt   [4096 * 128];
__device__ float g_Q    [4096 * 128];
__device__ float g_P    [8192 * 128];          // [Ps; Pt] stacked

// ---------------------------------------------------------------------------
// helpers
// ---------------------------------------------------------------------------
__device__ __forceinline__ uint32_t f2tf32(float x) {
    uint32_t r;
    asm("cvt.rna.tf32.f32 %0, %1;" : "=r"(r) : "f"(x));
    return r;
}

__device__ __forceinline__ void mma_tf32(float* c, const uint32_t* a, const uint32_t* b) {
    asm volatile(
        "mma.sync.aligned.m16n8k8.row.col.f32.tf32.tf32.f32 "
        "{%0,%1,%2,%3}, {%4,%5,%6,%7}, {%8,%9}, {%0,%1,%2,%3};\n"
        : "+f"(c[0]), "+f"(c[1]), "+f"(c[2]), "+f"(c[3])
        : "r"(a[0]), "r"(a[1]), "r"(a[2]), "r"(a[3]),
          "r"(b[0]), "r"(b[1]));
}

// FFMA-only exp: avoids the MUFU pipe entirely (16.7M exps would otherwise be
// MUFU-throughput-bound at ~125us chip-wide). Inputs are bounded by problem
// construction (no overflow per reference), |t| << 2^22 so the magic-round is
// exact; poly trunc error ~1e-7 over r in [-0.5,0.5].
__device__ __forceinline__ float fast_exp(float x) {
    const float LOG2E = 1.4426950408889634f;
    float t  = x * LOG2E;
    float kf = t + 12582912.0f;                 // 2^23 + 2^22: round-to-nearest-int
    int   k  = __float_as_int(kf) - 0x4B400000; // integer part
    float r  = t - (kf - 12582912.0f);          // r in [-0.5, 0.5]
    // 2^r Taylor, degree 6
    float p = 1.5403530e-4f;
    p = fmaf(p, r, 1.3333558e-3f);
    p = fmaf(p, r, 9.6181291e-3f);
    p = fmaf(p, r, 5.5504109e-2f);
    p = fmaf(p, r, 2.4022651e-1f);
    p = fmaf(p, r, 6.9314718e-1f);
    p = fmaf(p, r, 1.0f);
    return __int_as_float(__float_as_int(p) + (k << 23));
}

// ---------------------------------------------------------------------------
// tf32 tensor-core GEMM, fragment-packed smem, double buffered.
//   C[M,N] = A[M,K] @ B   (TRANSB=false: B [K,N] row-major; true: B [N,K] -> A@B^T)
// CTA tile 128x128x32, 512 threads = 16 warps (4M x 4N), warp tile 32x32.
// Packed A smem: [ks(4)][rb(8)][lane(32)][slot(4)] words, +4 pad per ks plane.
// Packed B smem: [ks(4)][nb(16)][lane(32)*2+slot(2)] with nb stride 66 words.
// gridDim.z > 1 => split-K partials at C + z*M*N (epi must be 0).
// epi: 0 none, 1 relu, 2 exp
// ---------------------------------------------------------------------------
constexpr int A_WORDS = 4 * (8 * 32 * 4 + 4);   // 4*1028 = 4112
constexpr int B_WORDS = 4 * (16 * 66);          // 4*1056 = 4224
constexpr int SMEM_BYTES = (2 * A_WORDS + 2 * B_WORDS) * 4;  // 66,688 B

template <bool TRANSB>
__global__ void __launch_bounds__(512, 1)
mma_gemm(const float* __restrict__ A, const float* __restrict__ B,
         float* __restrict__ C,
         int M, int N, int K, int lda, int ldb, int ldc,
         int kChunk, int epi)
{
    constexpr int BM = 128, BN = 128, BK = 32;
    constexpr int THREADS = 512;
    constexpr int KV = BK / 4;                      // 8
    constexpr int A_LOADS = (BM * KV) / THREADS;    // 2
    constexpr int B_LOADS = (BN * KV) / THREADS;    // 2

    extern __shared__ uint32_t sm[];
    uint32_t* AsBase = sm;                  // [2][A_WORDS]
    uint32_t* BsBase = sm + 2 * A_WORDS;    // [2][B_WORDS]

    const int tid  = threadIdx.x;
    const int lane = tid & 31;
    const int wid  = tid >> 5;
    const int wm   = wid & 3;               // 4 warps along M
    const int wn   = wid >> 2;              // 4 warps along N

    const int mBlock = blockIdx.y * BM;
    const int nBlock = blockIdx.x * BN;
    const int k0     = blockIdx.z * kChunk;

    if (gridDim.z > 1)
        C += (size_t)blockIdx.z * (size_t)M * (size_t)N;

    float4 pa[A_LOADS], pb[B_LOADS];

    float acc[2][4][4];
#pragma unroll
    for (int i = 0; i < 2; i++)
#pragma unroll
        for (int j = 0; j < 4; j++)
#pragma unroll
            for (int r = 0; r < 4; r++) acc[i][j][r] = 0.f;

    auto loadTiles = [&](int kt) {
#pragma unroll
        for (int i = 0; i < A_LOADS; i++) {
            int idx = tid + i * THREADS;
            int r   = idx >> 3;
            int kc  = (idx & 7) * 4;
            pa[i] = *reinterpret_cast<const float4*>(
                        &A[(size_t)(mBlock + r) * lda + kt + kc]);
        }
#pragma unroll
        for (int i = 0; i < B_LOADS; i++) {
            int idx = tid + i * THREADS;
            if constexpr (!TRANSB) {
                int k  = idx >> 5;
                int nc = (idx & 31) * 4;
                pb[i] = *reinterpret_cast<const float4*>(
                            &B[(size_t)(kt + k) * ldb + nBlock + nc]);
            } else {
                int n  = idx >> 3;
                int kc = (idx & 7) * 4;
                pb[i] = *reinterpret_cast<const float4*>(
                            &B[(size_t)(nBlock + n) * ldb + kt + kc]);
            }
        }
    };

    auto storeTiles = [&](int buf) {
        uint32_t* As = AsBase + buf * A_WORDS;
        uint32_t* Bs = BsBase + buf * B_WORDS;
#pragma unroll
        for (int i = 0; i < A_LOADS; i++) {
            int idx = tid + i * THREADS;
            int R   = idx >> 3;
            int kc  = (idx & 7) * 4;
            int ks   = kc >> 3;
            int shi  = (kc >> 2) & 1;
            int rb   = R >> 4;
            int slot = shi * 2 + ((R >> 3) & 1);
            int lb   = (R & 7) * 4;
            uint32_t* p = As + ks * 1028 + rb * 128 + slot;
            p[(lb + 0) * 4] = f2tf32(pa[i].x);
            p[(lb + 1) * 4] = f2tf32(pa[i].y);
            p[(lb + 2) * 4] = f2tf32(pa[i].z);
            p[(lb + 3) * 4] = f2tf32(pa[i].w);
        }
#pragma unroll
        for (int i = 0; i < B_LOADS; i++) {
            int idx = tid + i * THREADS;
            if constexpr (!TRANSB) {
                int k  = idx >> 5;
                int nc = (idx & 31) * 4;
                int ks   = k >> 3;
                int tt   = k & 7;
                int slot = tt >> 2;
                int t    = tt & 3;
                int nb   = nc >> 3;
                int g0   = nc & 7;              // 0 or 4
                uint32_t* p = Bs + ks * 1056 + nb * 66 + slot;
                p[((g0 + 0) * 4 + t) * 2] = f2tf32(pb[i].x);
                p[((g0 + 1) * 4 + t) * 2] = f2tf32(pb[i].y);
                p[((g0 + 2) * 4 + t) * 2] = f2tf32(pb[i].z);
                p[((g0 + 3) * 4 + t) * 2] = f2tf32(pb[i].w);
            } else {
                int n  = idx >> 3;
                int kc = (idx & 7) * 4;
                int ks   = kc >> 3;
                int slot = (kc >> 2) & 1;
                int nb   = n >> 3;
                int g    = n & 7;
                uint32_t* p = Bs + ks * 1056 + nb * 66 + slot;
                p[(g * 4 + 0) * 2] = f2tf32(pb[i].x);
                p[(g * 4 + 1) * 2] = f2tf32(pb[i].y);
                p[(g * 4 + 2) * 2] = f2tf32(pb[i].z);
                p[(g * 4 + 3) * 2] = f2tf32(pb[i].w);
            }
        }
    };

    auto computeTile = [&](int buf) {
        const uint32_t* As = AsBase + buf * A_WORDS;
        const uint32_t* Bs = BsBase + buf * B_WORDS;
#pragma unroll
        for (int ks = 0; ks < 4; ks++) {
            uint32_t af[2][4], bf[4][2];
#pragma unroll
            for (int mt = 0; mt < 2; mt++) {
                uint4 v = *reinterpret_cast<const uint4*>(
                    As + ks * 1028 + (wm * 2 + mt) * 128 + lane * 4);
                af[mt][0] = v.x; af[mt][1] = v.y; af[mt][2] = v.z; af[mt][3] = v.w;
            }
#pragma unroll
            for (int nt = 0; nt < 4; nt++) {
                uint2 v = *reinterpret_cast<const uint2*>(
                    Bs + ks * 1056 + (wn * 4 + nt) * 66 + lane * 2);
                bf[nt][0] = v.x; bf[nt][1] = v.y;
            }
#pragma unroll
            for (int mt = 0; mt < 2; mt++)
#pragma unroll
                for (int nt = 0; nt < 4; nt++)
                    mma_tf32(acc[mt][nt], af[mt], bf[nt]);
        }
    };

    const int kEnd = k0 + kChunk;
    loadTiles(k0);
    storeTiles(0);
    __syncthreads();
    int buf = 0;
    for (int kt = k0; kt < kEnd; kt += BK) {
        bool last = (kt + BK >= kEnd);
        if (!last) loadTiles(kt + BK);
        computeTile(buf);
        if (!last) {
            storeTiles(buf ^ 1);
            __syncthreads();
            buf ^= 1;
        }
    }

    const int g = lane >> 2;
    const int t = lane & 3;
#pragma unroll
    for (int mt = 0; mt < 2; mt++) {
#pragma unroll
        for (int nt = 0; nt < 4; nt++) {
            int r0 = mBlock + wm * 32 + mt * 16 + g;
            int c0 = nBlock + wn * 32 + nt * 8 + 2 * t;
            float2 v0 = make_float2(acc[mt][nt][0], acc[mt][nt][1]);
            float2 v1 = make_float2(acc[mt][nt][2], acc[mt][nt][3]);
            if (epi == 1) {
                v0.x = fmaxf(v0.x, 0.f); v0.y = fmaxf(v0.y, 0.f);
                v1.x = fmaxf(v1.x, 0.f); v1.y = fmaxf(v1.y, 0.f);
            } else if (epi == 2) {
                v0.x = fast_exp(v0.x); v0.y = fast_exp(v0.y);
                v1.x = fast_exp(v1.x); v1.y = fast_exp(v1.y);
            }
            *reinterpret_cast<float2*>(&C[(size_t)r0 * ldc + c0]) = v0;
            *reinterpret_cast<float2*>(&C[(size_t)(r0 + 8) * ldc + c0]) = v1;
        }
    }
}

// Split-K reduction (deterministic order).
__global__ void reduce_kernel(const float* __restrict__ part, float* __restrict__ out,
                              int MN, int splits)
{
    int i = (blockIdx.x * blockDim.x + threadIdx.x) * 4;
    if (i >= MN) return;
    float4 s = *reinterpret_cast<const float4*>(&part[i]);
    for (int z = 1; z < splits; z++) {
        float4 t = *reinterpret_cast<const float4*>(&part[(size_t)z * MN + i]);
        s.x += t.x; s.y += t.y; s.z += t.z; s.w += t.w;
    }
    *reinterpret_cast<float4*>(&out[i]) = s;
}

// Split-K reduce + de-interleave: part [z][4096][256] -> out [8192][128]
__global__ void reduce_deint_kernel(const float* __restrict__ part, float* __restrict__ out,
                                    int splits)
{
    int o = (blockIdx.x * blockDim.x + threadIdx.x) * 4;   // over 8192*128
    int r = o >> 7;
    int c = o & 127;
    size_t src = (size_t)(r & 4095) * 256 + ((r >> 12) << 7) + c;
    const int MN = 4096 * 256;
    float4 s = *reinterpret_cast<const float4*>(&part[src]);
    for (int z = 1; z < splits; z++) {
        float4 t = *reinterpret_cast<const float4*>(&part[(size_t)z * MN + src]);
        s.x += t.x; s.y += t.y; s.z += t.z; s.w += t.w;
    }
    *reinterpret_cast<float4*>(&out[o]) = s;
}

// Pack [Xs | Xt] -> out [4096][256]
__global__ void pack_kernel(const float* __restrict__ Xs, const float* __restrict__ Xt,
                            float* __restrict__ out)
{
    int o = (blockIdx.x * blockDim.x + threadIdx.x) * 4;   // over 4096*256
    int r = o >> 8;
    int c = o & 255;
    float4 v = (c < 128)
        ? *reinterpret_cast<const float4*>(&Xs[(size_t)r * 128 + c])
        : *reinterpret_cast<const float4*>(&Xt[(size_t)r * 128 + (c - 128)]);
    *reinterpret_cast<float4*>(&out[o]) = v;
}

// ---------------------------------------------------------------------------
// Launch helpers
// ---------------------------------------------------------------------------
template <bool TB>
static void mma_launch(const float* A, const float* B, float* C,
                       int M, int N, int K, int lda, int ldb, int ldc,
                       int splits, int epi)
{
    cudaFuncSetAttribute(mma_gemm<TB>, cudaFuncAttributeMaxDynamicSharedMemorySize,
                         SMEM_BYTES);
    dim3 grid(N / 128, M / 128, splits);
    mma_gemm<TB><<<grid, 512, SMEM_BYTES>>>(A, B, C, M, N, K, lda, ldb, ldc,
                                            K / splits, epi);
}

static void reduce_launch(const float* part, float* out, int MN, int splits)
{
    reduce_kernel<<<MN / (4 * 256), 256>>>(part, out, MN, splits);
}

// One GCN branch: Xout = relu((A @ relu((A@X)@W1)) @ W2)
static void gcn_branch(const float* A, const float* X,
                       const float* W1, const float* W2,
                       float* Xout, float* split, float* bufAX, float* bufH)
{
    mma_launch<false>(A, X, split, GN, DIN, GN, GN, DIN, DIN, 2, 0);
    reduce_launch(split, bufAX, GN * DIN, 2);
    mma_launch<false>(bufAX, W1, bufH, GN, DH, DIN, DIN, DH, DH, 1, 1);
    mma_launch<false>(A, bufH, split, GN, DH, GN, GN, DH, DH, 4, 0);
    reduce_launch(split, bufAX, GN * DH, 4);
    mma_launch<false>(bufAX, W2, Xout, GN, DH, DH, DH, DH, DH, 1, 1);
}

extern "C" void kernel_launch(void* const* d_in, const int* in_sizes, int n_in,
                              void* d_out, int out_size)
{
    const float* A_s = (const float*)d_in[0];
    const float* X_s = (const float*)d_in[1];
    const float* A_t = (const float*)d_in[2];
    const float* X_t = (const float*)d_in[3];
    const float* W1  = (const float*)d_in[4];
    const float* W2  = (const float*)d_in[5];
    const float* W3  = (const float*)d_in[6];
    const float* W4  = (const float*)d_in[7];

    float* out_st = (float*)d_out;                       // [8192, 128] = out_s|out_t
    float* S      = out_st + (size_t)2 * GN * DH;        // [4096, 4096]

    float *split, *bufAX, *bufH, *bXs, *bXt, *bQ, *bP;
    cudaGetSymbolAddress((void**)&split, g_split);
    cudaGetSymbolAddress((void**)&bufAX, g_bufAX);
    cudaGetSymbolAddress((void**)&bufH,  g_bufH);
    cudaGetSymbolAddress((void**)&bXs,   g_Xs);
    cudaGetSymbolAddress((void**)&bXt,   g_Xt);
    cudaGetSymbolAddress((void**)&bQ,    g_Q);
    cudaGetSymbolAddress((void**)&bP,    g_P);

    // GCN branches
    gcn_branch(A_s, X_s, W1, W2, bXs, split, bufAX, bufH);
    gcn_branch(A_t, X_t, W1, W2, bXt, split, bufAX, bufH);

    // Q = Xs @ W3
    mma_launch<false>(bXs, W3, bQ, GN, DH, DH, DH, DH, DH, 1, 0);

    // S = exp(Q @ Xt^T)  (written straight into output; FFMA fast_exp epilogue)
    mma_launch<true>(bQ, bXt, S, GN, GN, DH, DH, DH, GN, 1, 2);

    // XsXt = [Xs | Xt]  [4096, 256]  (reuse bufAX)
    pack_kernel<<<GN * 256 / (4 * 256), 256>>>(bXs, bXt, bufAX);

    // P_pair = S @ [Xs|Xt]  [4096,256], K=4096, split-K=4 (one pass over S)
    mma_launch<false>(S, bufAX, split, GN, 2 * DH, GN, GN, 2 * DH, 2 * DH, 4, 0);
    reduce_deint_kernel<<<8192 * 128 / (4 * 256), 256>>>(split, bP, 4);

    // [out_s; out_t] = [Ps; Pt] @ W4   (M = 8192, writes d_out directly)
    mma_launch<false>(bP, W4, out_st, 2 * GN, DH, DH, DH, DH, DH, 1, 0);
}

// round 11
// speedup vs baseline: 1.0211x; 1.0161x over previous
#include <cuda_runtime.h>
#include <math.h>
#include <stdint.h>

// ---------------------------------------------------------------------------
//   N = 4096, DIM_IN = 256, DIM_H = 128, DIM_OUT = 128
//   Xs = relu((A_s@X_s)@W1); Xs = relu((A_s@Xs)@W2)   (same for t)
//   S  = exp((Xs@W3)@Xt^T)
//   out_s = (S@Xs)@W4 ; out_t = (S@Xt)@W4
// Output: [out_s | out_t | S]
// NOTE: tcgen05 is NOT available — harness compiles PTX to .target sm_103
// (no 'a' suffix); arch-specific instructions fail ptxas. HMMA mma.sync only.
// ---------------------------------------------------------------------------

#define GN    4096
#define DIN   256
#define DH    128

__device__ float g_split[4u * 4096u * 256u];   // split-K partials
__device__ float g_bufAX[4096 * 256];          // A@X intermediate / XsXt pack
__device__ float g_bufH [4096 * 128];
__device__ float g_Xs   [4096 * 128];
__device__ float g_Xt   [4096 * 128];
__device__ float g_Q    [4096 * 128];
__device__ float g_P    [8192 * 128];          // [Ps; Pt] stacked

// ---------------------------------------------------------------------------
// helpers
// ---------------------------------------------------------------------------
__device__ __forceinline__ uint32_t f2tf32(float x) {
    uint32_t r;
    asm("cvt.rna.tf32.f32 %0, %1;" : "=r"(r) : "f"(x));
    return r;
}

__device__ __forceinline__ void mma_tf32(float* c, const uint32_t* a, const uint32_t* b) {
    asm volatile(
        "mma.sync.aligned.m16n8k8.row.col.f32.tf32.tf32.f32 "
        "{%0,%1,%2,%3}, {%4,%5,%6,%7}, {%8,%9}, {%0,%1,%2,%3};\n"
        : "+f"(c[0]), "+f"(c[1]), "+f"(c[2]), "+f"(c[3])
        : "r"(a[0]), "r"(a[1]), "r"(a[2]), "r"(a[3]),
          "r"(b[0]), "r"(b[1]));
}

// FFMA-only exp (MUFU would bottleneck 16.7M exps at ~125us chip-wide).
// Inputs bounded by problem construction; poly trunc err ~1e-7 on [-0.5,0.5].
__device__ __forceinline__ float fast_exp(float x) {
    const float LOG2E = 1.4426950408889634f;
    float t  = x * LOG2E;
    float kf = t + 12582912.0f;                 // 2^23 + 2^22 round
    int   k  = __float_as_int(kf) - 0x4B400000;
    float r  = t - (kf - 12582912.0f);
    float p = 1.5403530e-4f;
    p = fmaf(p, r, 1.3333558e-3f);
    p = fmaf(p, r, 9.6181291e-3f);
    p = fmaf(p, r, 5.5504109e-2f);
    p = fmaf(p, r, 2.4022651e-1f);
    p = fmaf(p, r, 6.9314718e-1f);
    p = fmaf(p, r, 1.0f);
    return __int_as_float(__float_as_int(p) + (k << 23));
}

// ---------------------------------------------------------------------------
// tf32 tensor-core GEMM, fragment-packed smem, double buffered.
//   C[M,N] = A[M,K] @ B   (TRANSB=false: B [K,N] row-major; true: B [N,K] -> A@B^T)
// CTA tile BM x 128 x 32 (BM = 128 or 256), 512 threads = 16 warps (4M x 4N),
// warp tile (BM/4) x 32, m16n8k8 HMMA.
// Packed A smem: per ks plane [rb(BM/16)][lane(32)][slot(4)] + 4 pad words.
// Packed B smem: per ks plane [nb(16)][66 words].
// All smem store offsets / global pointers precomputed (ALU relief).
// gridDim.z > 1 => split-K partials at C + z*M*N (EPI must be 0).
// EPI: 0 none, 1 relu, 2 exp
// ---------------------------------------------------------------------------
template <int BM, bool TRANSB, int EPI>
__global__ void __launch_bounds__(512, 1)
mma_gemm(const float* __restrict__ A, const float* __restrict__ B,
         float* __restrict__ C,
         int M, int N, int K, int lda, int ldb, int ldc, int kChunk)
{
    constexpr int BN = 128, BK = 32, THREADS = 512;
    constexpr int MT      = BM / 64;            // m16 tiles per warp (2 or 4)
    constexpr int RB      = BM / 16;
    constexpr int PLANE   = RB * 128 + 4;       // words per ks plane (A)
    constexpr int AW      = 4 * PLANE;
    constexpr int BW      = 4 * 1056;
    constexpr int A_LOADS = BM / 64;            // float4 per thread (2 or 4)
    constexpr int B_LOADS = 2;
    constexpr int BSTRIDE = TRANSB ? 2 : 8;     // word stride between B store elems

    extern __shared__ uint32_t sm[];
    uint32_t* const Abuf[2] = { sm, sm + AW };
    uint32_t* const Bbuf[2] = { sm + 2 * AW, sm + 2 * AW + BW };

    const int tid  = threadIdx.x;
    const int lane = tid & 31;
    const int wid  = tid >> 5;
    const int wm   = wid & 3;                   // 4 warps along M
    const int wn   = wid >> 2;                  // 4 warps along N

    const int mBlock = blockIdx.y * BM;
    const int nBlock = blockIdx.x * BN;
    const int k0     = blockIdx.z * kChunk;

    if (gridDim.z > 1)
        C += (size_t)blockIdx.z * (size_t)M * (size_t)N;

    // ---- precomputed global sources + smem store offsets --------------------
    const float* aSrc[A_LOADS];
    uint32_t     aOff[A_LOADS];
#pragma unroll
    for (int i = 0; i < A_LOADS; i++) {
        int idx = tid + i * THREADS;
        int r = idx >> 3, kc = (idx & 7) * 4;
        aSrc[i] = A + (size_t)(mBlock + r) * lda + k0 + kc;
        int ks = kc >> 3, shi = (kc >> 2) & 1;
        int rb = r >> 4, slot = shi * 2 + ((r >> 3) & 1), lb = (r & 7) * 4;
        aOff[i] = ks * PLANE + rb * 128 + slot + lb * 4;
    }
    const float* bSrc[B_LOADS];
    uint32_t     bOff[B_LOADS];
#pragma unroll
    for (int i = 0; i < B_LOADS; i++) {
        int idx = tid + i * THREADS;
        if constexpr (!TRANSB) {
            int k = idx >> 5, nc = (idx & 31) * 4;
            bSrc[i] = B + (size_t)(k0 + k) * ldb + nBlock + nc;
            int ks = k >> 3, tt = k & 7, slot = tt >> 2, t = tt & 3;
            int nb = nc >> 3, g0 = nc & 7;
            bOff[i] = ks * 1056 + nb * 66 + slot + (g0 * 4 + t) * 2;
        } else {
            int n = idx >> 3, kc = (idx & 7) * 4;
            bSrc[i] = B + (size_t)(nBlock + n) * ldb + k0 + kc;
            int ks = kc >> 3, slot = (kc >> 2) & 1, nb = n >> 3, g = n & 7;
            bOff[i] = ks * 1056 + nb * 66 + slot + g * 8;
        }
    }
    const size_t bAdv = TRANSB ? (size_t)BK : (size_t)BK * ldb;
    const int aCol = wm * (MT * 128) + lane * 4;   // compute-loop A base (words)
    const int bCol = wn * (4 * 66) + lane * 2;     // compute-loop B base (words)

    float acc[MT][4][4];
#pragma unroll
    for (int i = 0; i < MT; i++)
#pragma unroll
        for (int j = 0; j < 4; j++)
#pragma unroll
            for (int r = 0; r < 4; r++) acc[i][j][r] = 0.f;

    float4 pa[A_LOADS], pb[B_LOADS];

    auto loadTiles = [&]() {
#pragma unroll
        for (int i = 0; i < A_LOADS; i++) {
            pa[i] = *reinterpret_cast<const float4*>(aSrc[i]);
            aSrc[i] += BK;
        }
#pragma unroll
        for (int i = 0; i < B_LOADS; i++) {
            pb[i] = *reinterpret_cast<const float4*>(bSrc[i]);
            bSrc[i] += bAdv;
        }
    };

    auto storeTiles = [&](int buf) {
        uint32_t* const As = Abuf[buf];
        uint32_t* const Bs = Bbuf[buf];
#pragma unroll
        for (int i = 0; i < A_LOADS; i++) {
            uint32_t* p = As + aOff[i];
            p[0]  = f2tf32(pa[i].x);
            p[4]  = f2tf32(pa[i].y);
            p[8]  = f2tf32(pa[i].z);
            p[12] = f2tf32(pa[i].w);
        }
#pragma unroll
        for (int i = 0; i < B_LOADS; i++) {
            uint32_t* q = Bs + bOff[i];
            q[0 * BSTRIDE] = f2tf32(pb[i].x);
            q[1 * BSTRIDE] = f2tf32(pb[i].y);
            q[2 * BSTRIDE] = f2tf32(pb[i].z);
            q[3 * BSTRIDE] = f2tf32(pb[i].w);
        }
    };

    auto computeTile = [&](int buf) {
        const uint32_t* const As = Abuf[buf] + aCol;
        const uint32_t* const Bs = Bbuf[buf] + bCol;
#pragma unroll
        for (int ks = 0; ks < 4; ks++) {
            uint32_t af[MT][4], bf[4][2];
#pragma unroll
            for (int mt = 0; mt < MT; mt++) {
                uint4 v = *reinterpret_cast<const uint4*>(As + ks * PLANE + mt * 128);
                af[mt][0] = v.x; af[mt][1] = v.y; af[mt][2] = v.z; af[mt][3] = v.w;
            }
#pragma unroll
            for (int nt = 0; nt < 4; nt++) {
                uint2 v = *reinterpret_cast<const uint2*>(Bs + ks * 1056 + nt * 66);
                bf[nt][0] = v.x; bf[nt][1] = v.y;
            }
#pragma unroll
            for (int mt = 0; mt < MT; mt++)
#pragma unroll
                for (int nt = 0; nt < 4; nt++)
                    mma_tf32(acc[mt][nt], af[mt], bf[nt]);
        }
    };

    const int numIter = kChunk / BK;
    loadTiles();
    storeTiles(0);
    __syncthreads();
    int buf = 0;
    for (int it = 0; it < numIter; it++) {
        bool last = (it == numIter - 1);
        if (!last) loadTiles();
        computeTile(buf);
        if (!last) {
            storeTiles(buf ^ 1);
            __syncthreads();
            buf ^= 1;
        }
    }

    const int g = lane >> 2;
    const int t = lane & 3;
#pragma unroll
    for (int mt = 0; mt < MT; mt++) {
#pragma unroll
        for (int nt = 0; nt < 4; nt++) {
            int r0 = mBlock + wm * (MT * 16) + mt * 16 + g;
            int c0 = nBlock + wn * 32 + nt * 8 + 2 * t;
            float2 v0 = make_float2(acc[mt][nt][0], acc[mt][nt][1]);
            float2 v1 = make_float2(acc[mt][nt][2], acc[mt][nt][3]);
            if (EPI == 1) {
                v0.x = fmaxf(v0.x, 0.f); v0.y = fmaxf(v0.y, 0.f);
                v1.x = fmaxf(v1.x, 0.f); v1.y = fmaxf(v1.y, 0.f);
            } else if (EPI == 2) {
                v0.x = fast_exp(v0.x); v0.y = fast_exp(v0.y);
                v1.x = fast_exp(v1.x); v1.y = fast_exp(v1.y);
            }
            *reinterpret_cast<float2*>(&C[(size_t)r0 * ldc + c0]) = v0;
            *reinterpret_cast<float2*>(&C[(size_t)(r0 + 8) * ldc + c0]) = v1;
        }
    }
}

// Split-K reduction (deterministic order).
__global__ void reduce_kernel(const float* __restrict__ part, float* __restrict__ out,
                              int MN, int splits)
{
    int i = (blockIdx.x * blockDim.x + threadIdx.x) * 4;
    if (i >= MN) return;
    float4 s = *reinterpret_cast<const float4*>(&part[i]);
    for (int z = 1; z < splits; z++) {
        float4 t = *reinterpret_cast<const float4*>(&part[(size_t)z * MN + i]);
        s.x += t.x; s.y += t.y; s.z += t.z; s.w += t.w;
    }
    *reinterpret_cast<float4*>(&out[i]) = s;
}

// Split-K reduce + de-interleave: part [z][4096][256] -> out [8192][128]
__global__ void reduce_deint_kernel(const float* __restrict__ part, float* __restrict__ out,
                                    int splits)
{
    int o = (blockIdx.x * blockDim.x + threadIdx.x) * 4;   // over 8192*128
    int r = o >> 7;
    int c = o & 127;
    size_t src = (size_t)(r & 4095) * 256 + ((r >> 12) << 7) + c;
    const int MN = 4096 * 256;
    float4 s = *reinterpret_cast<const float4*>(&part[src]);
    for (int z = 1; z < splits; z++) {
        float4 t = *reinterpret_cast<const float4*>(&part[(size_t)z * MN + src]);
        s.x += t.x; s.y += t.y; s.z += t.z; s.w += t.w;
    }
    *reinterpret_cast<float4*>(&out[o]) = s;
}

// Pack [Xs | Xt] -> out [4096][256]
__global__ void pack_kernel(const float* __restrict__ Xs, const float* __restrict__ Xt,
                            float* __restrict__ out)
{
    int o = (blockIdx.x * blockDim.x + threadIdx.x) * 4;   // over 4096*256
    int r = o >> 8;
    int c = o & 255;
    float4 v = (c < 128)
        ? *reinterpret_cast<const float4*>(&Xs[(size_t)r * 128 + c])
        : *reinterpret_cast<const float4*>(&Xt[(size_t)r * 128 + (c - 128)]);
    *reinterpret_cast<float4*>(&out[o]) = v;
}

// ---------------------------------------------------------------------------
// Launch helpers
// ---------------------------------------------------------------------------
template <int BM, bool TB, int EPI>
static void mma_launch(const float* A, const float* B, float* C,
                       int M, int N, int K, int lda, int ldb, int ldc, int splits)
{
    constexpr int RB = BM / 16;
    constexpr int AW = 4 * (RB * 128 + 4);
    constexpr int BW = 4 * 1056;
    constexpr int SMEM = (2 * AW + 2 * BW) * 4;
    cudaFuncSetAttribute(mma_gemm<BM, TB, EPI>,
                         cudaFuncAttributeMaxDynamicSharedMemorySize, SMEM);
    dim3 grid(N / 128, M / BM, splits);
    mma_gemm<BM, TB, EPI><<<grid, 512, SMEM>>>(A, B, C, M, N, K, lda, ldb, ldc,
                                               K / splits);
}

static void reduce_launch(const float* part, float* out, int MN, int splits)
{
    reduce_kernel<<<MN / (4 * 256), 256>>>(part, out, MN, splits);
}

// One GCN branch: Xout = relu((A @ relu((A@X)@W1)) @ W2)
static void gcn_branch(const float* A, const float* X,
                       const float* W1, const float* W2,
                       float* Xout, float* split, float* bufAX, float* bufH)
{
    // AX = A@X  [4096,256] K=4096, BM=256, split-K=4 -> grid(2,16,4)=128 CTAs
    mma_launch<256, false, 0>(A, X, split, GN, DIN, GN, GN, DIN, DIN, 4);
    reduce_launch(split, bufAX, GN * DIN, 4);
    // H = relu(AX @ W1)  [4096,128] K=256
    mma_launch<128, false, 1>(bufAX, W1, bufH, GN, DH, DIN, DIN, DH, DH, 1);
    // AH = A@H  [4096,128] K=4096, BM=256, split-K=8 -> grid(1,16,8)=128 CTAs
    mma_launch<256, false, 0>(A, bufH, split, GN, DH, GN, GN, DH, DH, 8);
    reduce_launch(split, bufAX, GN * DH, 8);
    // Xout = relu(AH @ W2)
    mma_launch<128, false, 1>(bufAX, W2, Xout, GN, DH, DH, DH, DH, DH, 1);
}

extern "C" void kernel_launch(void* const* d_in, const int* in_sizes, int n_in,
                              void* d_out, int out_size)
{
    const float* A_s = (const float*)d_in[0];
    const float* X_s = (const float*)d_in[1];
    const float* A_t = (const float*)d_in[2];
    const float* X_t = (const float*)d_in[3];
    const float* W1  = (const float*)d_in[4];
    const float* W2  = (const float*)d_in[5];
    const float* W3  = (const float*)d_in[6];
    const float* W4  = (const float*)d_in[7];

    float* out_st = (float*)d_out;                       // [8192, 128] = out_s|out_t
    float* S      = out_st + (size_t)2 * GN * DH;        // [4096, 4096]

    float *split, *bufAX, *bufH, *bXs, *bXt, *bQ, *bP;
    cudaGetSymbolAddress((void**)&split, g_split);
    cudaGetSymbolAddress((void**)&bufAX, g_bufAX);
    cudaGetSymbolAddress((void**)&bufH,  g_bufH);
    cudaGetSymbolAddress((void**)&bXs,   g_Xs);
    cudaGetSymbolAddress((void**)&bXt,   g_Xt);
    cudaGetSymbolAddress((void**)&bQ,    g_Q);
    cudaGetSymbolAddress((void**)&bP,    g_P);

    // GCN branches
    gcn_branch(A_s, X_s, W1, W2, bXs, split, bufAX, bufH);
    gcn_branch(A_t, X_t, W1, W2, bXt, split, bufAX, bufH);

    // Q = Xs @ W3
    mma_launch<128, false, 0>(bXs, W3, bQ, GN, DH, DH, DH, DH, DH, 1);

    // S = exp(Q @ Xt^T)  BM=256 -> grid(32,16)=512 CTAs, fast_exp epilogue
    mma_launch<256, true, 2>(bQ, bXt, S, GN, GN, DH, DH, DH, GN, 1);

    // XsXt = [Xs | Xt]  [4096, 256]  (reuse bufAX)
    pack_kernel<<<GN * 256 / (4 * 256), 256>>>(bXs, bXt, bufAX);

    // P_pair = S @ [Xs|Xt]  [4096,256], K=4096, BM=256, split-K=4 (one pass over S)
    mma_launch<256, false, 0>(S, bufAX, split, GN, 2 * DH, GN, GN, 2 * DH, 2 * DH, 4);
    reduce_deint_kernel<<<8192 * 128 / (4 * 256), 256>>>(split, bP, 4);

    // [out_s; out_t] = [Ps; Pt] @ W4   (M = 8192, writes d_out directly)
    mma_launch<128, false, 0>(bP, W4, out_st, 2 * GN, DH, DH, DH, DH, DH, 1);
}

// round 12
// speedup vs baseline: 1.0215x; 1.0004x over previous
#include <cuda_runtime.h>
#include <math.h>
#include <stdint.h>

// ---------------------------------------------------------------------------
//   N = 4096, DIM_IN = 256, DIM_H = 128, DIM_OUT = 128
//   Xs = relu((A_s@X_s)@W1); Xs = relu((A_s@Xs)@W2)   (same for t)
//   S  = exp((Xs@W3)@Xt^T)
//   out_s = (S@Xs)@W4 ; out_t = (S@Xt)@W4
// Output: [out_s | out_t | S]
// NOTE: tcgen05 is NOT available — harness compiles PTX to .target sm_103
// (no 'a' suffix); arch-specific instructions fail ptxas. HMMA mma.sync only.
// ---------------------------------------------------------------------------

#define GN    4096
#define DIN   256
#define DH    128

__device__ float g_split[4u * 4096u * 256u];   // split-K partials
__device__ float g_bufAX[4096 * 256];          // A@X intermediate / XsXt pack
__device__ float g_bufH [4096 * 128];
__device__ float g_Xs   [4096 * 128];
__device__ float g_Xt   [4096 * 128];
__device__ float g_Q    [4096 * 128];
__device__ float g_P    [8192 * 128];          // [Ps; Pt] stacked

// ---------------------------------------------------------------------------
// helpers
// ---------------------------------------------------------------------------
__device__ __forceinline__ uint32_t f2tf32(float x) {
    uint32_t r;
    asm("cvt.rna.tf32.f32 %0, %1;" : "=r"(r) : "f"(x));
    return r;
}

__device__ __forceinline__ void mma_tf32(float* c, const uint32_t* a, const uint32_t* b) {
    asm volatile(
        "mma.sync.aligned.m16n8k8.row.col.f32.tf32.tf32.f32 "
        "{%0,%1,%2,%3}, {%4,%5,%6,%7}, {%8,%9}, {%0,%1,%2,%3};\n"
        : "+f"(c[0]), "+f"(c[1]), "+f"(c[2]), "+f"(c[3])
        : "r"(a[0]), "r"(a[1]), "r"(a[2]), "r"(a[3]),
          "r"(b[0]), "r"(b[1]));
}

// FFMA-only exp (MUFU would bottleneck 16.7M exps at ~125us chip-wide).
// Inputs bounded by problem construction; poly trunc err ~1e-7 on [-0.5,0.5].
__device__ __forceinline__ float fast_exp(float x) {
    const float LOG2E = 1.4426950408889634f;
    float t  = x * LOG2E;
    float kf = t + 12582912.0f;                 // 2^23 + 2^22 round
    int   k  = __float_as_int(kf) - 0x4B400000;
    float r  = t - (kf - 12582912.0f);
    float p = 1.5403530e-4f;
    p = fmaf(p, r, 1.3333558e-3f);
    p = fmaf(p, r, 9.6181291e-3f);
    p = fmaf(p, r, 5.5504109e-2f);
    p = fmaf(p, r, 2.4022651e-1f);
    p = fmaf(p, r, 6.9314718e-1f);
    p = fmaf(p, r, 1.0f);
    return __int_as_float(__float_as_int(p) + (k << 23));
}

// ---------------------------------------------------------------------------
// tf32 tensor-core GEMM, fragment-packed smem, double buffered.
//   C[M,N] = A[M,K] @ B   (TRANSB=false: B [K,N] row-major; true: B [N,K] -> A@B^T)
// CTA tile BM x 128 x 32 (BM = 128 or 256), 512 threads = 16 warps (4M x 4N),
// warp tile (BM/4) x 32, m16n8k8 HMMA.
// Packed A smem: per ks plane [rb(BM/16)][lane(32)][slot(4)] + 4 pad words.
// Packed B smem: per ks plane [nb(16)][66 words].
// All smem store offsets / global pointers precomputed (ALU relief).
// gridDim.z > 1 => split-K partials at C + z*M*N (EPI must be 0).
// EPI: 0 none, 1 relu, 2 exp
// ---------------------------------------------------------------------------
template <int BM, bool TRANSB, int EPI>
__global__ void __launch_bounds__(512, 1)
mma_gemm(const float* __restrict__ A, const float* __restrict__ B,
         float* __restrict__ C,
         int M, int N, int K, int lda, int ldb, int ldc, int kChunk)
{
    constexpr int BN = 128, BK = 32, THREADS = 512;
    constexpr int MT      = BM / 64;            // m16 tiles per warp (2 or 4)
    constexpr int RB      = BM / 16;
    constexpr int PLANE   = RB * 128 + 4;       // words per ks plane (A)
    constexpr int AW      = 4 * PLANE;
    constexpr int BW      = 4 * 1056;
    constexpr int A_LOADS = BM / 64;            // float4 per thread (2 or 4)
    constexpr int B_LOADS = 2;
    constexpr int BSTRIDE = TRANSB ? 2 : 8;     // word stride between B store elems

    extern __shared__ uint32_t sm[];
    uint32_t* const Abuf[2] = { sm, sm + AW };
    uint32_t* const Bbuf[2] = { sm + 2 * AW, sm + 2 * AW + BW };

    const int tid  = threadIdx.x;
    const int lane = tid & 31;
    const int wid  = tid >> 5;
    const int wm   = wid & 3;                   // 4 warps along M
    const int wn   = wid >> 2;                  // 4 warps along N

    const int mBlock = blockIdx.y * BM;
    const int nBlock = blockIdx.x * BN;
    const int k0     = blockIdx.z * kChunk;

    if (gridDim.z > 1)
        C += (size_t)blockIdx.z * (size_t)M * (size_t)N;

    // ---- precomputed global sources + smem store offsets --------------------
    const float* aSrc[A_LOADS];
    uint32_t     aOff[A_LOADS];
#pragma unroll
    for (int i = 0; i < A_LOADS; i++) {
        int idx = tid + i * THREADS;
        int r = idx >> 3, kc = (idx & 7) * 4;
        aSrc[i] = A + (size_t)(mBlock + r) * lda + k0 + kc;
        int ks = kc >> 3, shi = (kc >> 2) & 1;
        int rb = r >> 4, slot = shi * 2 + ((r >> 3) & 1), lb = (r & 7) * 4;
        aOff[i] = ks * PLANE + rb * 128 + slot + lb * 4;
    }
    const float* bSrc[B_LOADS];
    uint32_t     bOff[B_LOADS];
#pragma unroll
    for (int i = 0; i < B_LOADS; i++) {
        int idx = tid + i * THREADS;
        if constexpr (!TRANSB) {
            int k = idx >> 5, nc = (idx & 31) * 4;
            bSrc[i] = B + (size_t)(k0 + k) * ldb + nBlock + nc;
            int ks = k >> 3, tt = k & 7, slot = tt >> 2, t = tt & 3;
            int nb = nc >> 3, g0 = nc & 7;
            bOff[i] = ks * 1056 + nb * 66 + slot + (g0 * 4 + t) * 2;
        } else {
            int n = idx >> 3, kc = (idx & 7) * 4;
            bSrc[i] = B + (size_t)(nBlock + n) * ldb + k0 + kc;
            int ks = kc >> 3, slot = (kc >> 2) & 1, nb = n >> 3, g = n & 7;
            bOff[i] = ks * 1056 + nb * 66 + slot + g * 8;
        }
    }
    const size_t bAdv = TRANSB ? (size_t)BK : (size_t)BK * ldb;
    const int aCol = wm * (MT * 128) + lane * 4;   // compute-loop A base (words)
    const int bCol = wn * (4 * 66) + lane * 2;     // compute-loop B base (words)

    float acc[MT][4][4];
#pragma unroll
    for (int i = 0; i < MT; i++)
#pragma unroll
        for (int j = 0; j < 4; j++)
#pragma unroll
            for (int r = 0; r < 4; r++) acc[i][j][r] = 0.f;

    float4 pa[A_LOADS], pb[B_LOADS];

    auto loadTiles = [&]() {
#pragma unroll
        for (int i = 0; i < A_LOADS; i++) {
            pa[i] = *reinterpret_cast<const float4*>(aSrc[i]);
            aSrc[i] += BK;
        }
#pragma unroll
        for (int i = 0; i < B_LOADS; i++) {
            pb[i] = *reinterpret_cast<const float4*>(bSrc[i]);
            bSrc[i] += bAdv;
        }
    };

    auto storeTiles = [&](int buf) {
        uint32_t* const As = Abuf[buf];
        uint32_t* const Bs = Bbuf[buf];
#pragma unroll
        for (int i = 0; i < A_LOADS; i++) {
            uint32_t* p = As + aOff[i];
            p[0]  = f2tf32(pa[i].x);
            p[4]  = f2tf32(pa[i].y);
            p[8]  = f2tf32(pa[i].z);
            p[12] = f2tf32(pa[i].w);
        }
#pragma unroll
        for (int i = 0; i < B_LOADS; i++) {
            uint32_t* q = Bs + bOff[i];
            q[0 * BSTRIDE] = f2tf32(pb[i].x);
            q[1 * BSTRIDE] = f2tf32(pb[i].y);
            q[2 * BSTRIDE] = f2tf32(pb[i].z);
            q[3 * BSTRIDE] = f2tf32(pb[i].w);
        }
    };

    auto computeTile = [&](int buf) {
        const uint32_t* const As = Abuf[buf] + aCol;
        const uint32_t* const Bs = Bbuf[buf] + bCol;
#pragma unroll
        for (int ks = 0; ks < 4; ks++) {
            uint32_t af[MT][4], bf[4][2];
#pragma unroll
            for (int mt = 0; mt < MT; mt++) {
                uint4 v = *reinterpret_cast<const uint4*>(As + ks * PLANE + mt * 128);
                af[mt][0] = v.x; af[mt][1] = v.y; af[mt][2] = v.z; af[mt][3] = v.w;
            }
#pragma unroll
            for (int nt = 0; nt < 4; nt++) {
                uint2 v = *reinterpret_cast<const uint2*>(Bs + ks * 1056 + nt * 66);
                bf[nt][0] = v.x; bf[nt][1] = v.y;
            }
#pragma unroll
            for (int mt = 0; mt < MT; mt++)
#pragma unroll
                for (int nt = 0; nt < 4; nt++)
                    mma_tf32(acc[mt][nt], af[mt], bf[nt]);
        }
    };

    const int numIter = kChunk / BK;
    loadTiles();
    storeTiles(0);
    __syncthreads();
    int buf = 0;
    for (int it = 0; it < numIter; it++) {
        bool last = (it == numIter - 1);
        if (!last) loadTiles();
        computeTile(buf);
        if (!last) {
            storeTiles(buf ^ 1);
            __syncthreads();
            buf ^= 1;
        }
    }

    const int g = lane >> 2;
    const int t = lane & 3;
#pragma unroll
    for (int mt = 0; mt < MT; mt++) {
#pragma unroll
        for (int nt = 0; nt < 4; nt++) {
            int r0 = mBlock + wm * (MT * 16) + mt * 16 + g;
            int c0 = nBlock + wn * 32 + nt * 8 + 2 * t;
            float2 v0 = make_float2(acc[mt][nt][0], acc[mt][nt][1]);
            float2 v1 = make_float2(acc[mt][nt][2], acc[mt][nt][3]);
            if (EPI == 1) {
                v0.x = fmaxf(v0.x, 0.f); v0.y = fmaxf(v0.y, 0.f);
                v1.x = fmaxf(v1.x, 0.f); v1.y = fmaxf(v1.y, 0.f);
            } else if (EPI == 2) {
                v0.x = fast_exp(v0.x); v0.y = fast_exp(v0.y);
                v1.x = fast_exp(v1.x); v1.y = fast_exp(v1.y);
            }
            *reinterpret_cast<float2*>(&C[(size_t)r0 * ldc + c0]) = v0;
            *reinterpret_cast<float2*>(&C[(size_t)(r0 + 8) * ldc + c0]) = v1;
        }
    }
}

// Split-K reduction (deterministic order).
__global__ void reduce_kernel(const float* __restrict__ part, float* __restrict__ out,
                              int MN, int splits)
{
    int i = (blockIdx.x * blockDim.x + threadIdx.x) * 4;
    if (i >= MN) return;
    float4 s = *reinterpret_cast<const float4*>(&part[i]);
    for (int z = 1; z < splits; z++) {
        float4 t = *reinterpret_cast<const float4*>(&part[(size_t)z * MN + i]);
        s.x += t.x; s.y += t.y; s.z += t.z; s.w += t.w;
    }
    *reinterpret_cast<float4*>(&out[i]) = s;
}

// Split-K reduce + de-interleave: part [z][4096][256] -> out [8192][128]
__global__ void reduce_deint_kernel(const float* __restrict__ part, float* __restrict__ out,
                                    int splits)
{
    int o = (blockIdx.x * blockDim.x + threadIdx.x) * 4;   // over 8192*128
    int r = o >> 7;
    int c = o & 127;
    size_t src = (size_t)(r & 4095) * 256 + ((r >> 12) << 7) + c;
    const int MN = 4096 * 256;
    float4 s = *reinterpret_cast<const float4*>(&part[src]);
    for (int z = 1; z < splits; z++) {
        float4 t = *reinterpret_cast<const float4*>(&part[(size_t)z * MN + src]);
        s.x += t.x; s.y += t.y; s.z += t.z; s.w += t.w;
    }
    *reinterpret_cast<float4*>(&out[o]) = s;
}

// Pack [Xs | Xt] -> out [4096][256]
__global__ void pack_kernel(const float* __restrict__ Xs, const float* __restrict__ Xt,
                            float* __restrict__ out)
{
    int o = (blockIdx.x * blockDim.x + threadIdx.x) * 4;   // over 4096*256
    int r = o >> 8;
    int c = o & 255;
    float4 v = (c < 128)
        ? *reinterpret_cast<const float4*>(&Xs[(size_t)r * 128 + c])
        : *reinterpret_cast<const float4*>(&Xt[(size_t)r * 128 + (c - 128)]);
    *reinterpret_cast<float4*>(&out[o]) = v;
}

// ---------------------------------------------------------------------------
// Launch helpers
// ---------------------------------------------------------------------------
template <int BM, bool TB, int EPI>
static void mma_launch(const float* A, const float* B, float* C,
                       int M, int N, int K, int lda, int ldb, int ldc, int splits)
{
    constexpr int RB = BM / 16;
    constexpr int AW = 4 * (RB * 128 + 4);
    constexpr int BW = 4 * 1056;
    constexpr int SMEM = (2 * AW + 2 * BW) * 4;
    cudaFuncSetAttribute(mma_gemm<BM, TB, EPI>,
                         cudaFuncAttributeMaxDynamicSharedMemorySize, SMEM);
    dim3 grid(N / 128, M / BM, splits);
    mma_gemm<BM, TB, EPI><<<grid, 512, SMEM>>>(A, B, C, M, N, K, lda, ldb, ldc,
                                               K / splits);
}

static void reduce_launch(const float* part, float* out, int MN, int splits)
{
    reduce_kernel<<<MN / (4 * 256), 256>>>(part, out, MN, splits);
}

// One GCN branch: Xout = relu((A @ relu((A@X)@W1)) @ W2)
static void gcn_branch(const float* A, const float* X,
                       const float* W1, const float* W2,
                       float* Xout, float* split, float* bufAX, float* bufH)
{
    // AX = A@X  [4096,256] K=4096, BM=256, split-K=4 -> grid(2,16,4)=128 CTAs
    mma_launch<256, false, 0>(A, X, split, GN, DIN, GN, GN, DIN, DIN, 4);
    reduce_launch(split, bufAX, GN * DIN, 4);
    // H = relu(AX @ W1)  [4096,128] K=256
    mma_launch<128, false, 1>(bufAX, W1, bufH, GN, DH, DIN, DIN, DH, DH, 1);
    // AH = A@H  [4096,128] K=4096, BM=256, split-K=8 -> grid(1,16,8)=128 CTAs
    mma_launch<256, false, 0>(A, bufH, split, GN, DH, GN, GN, DH, DH, 8);
    reduce_launch(split, bufAX, GN * DH, 8);
    // Xout = relu(AH @ W2)
    mma_launch<128, false, 1>(bufAX, W2, Xout, GN, DH, DH, DH, DH, DH, 1);
}

extern "C" void kernel_launch(void* const* d_in, const int* in_sizes, int n_in,
                              void* d_out, int out_size)
{
    const float* A_s = (const float*)d_in[0];
    const float* X_s = (const float*)d_in[1];
    const float* A_t = (const float*)d_in[2];
    const float* X_t = (const float*)d_in[3];
    const float* W1  = (const float*)d_in[4];
    const float* W2  = (const float*)d_in[5];
    const float* W3  = (const float*)d_in[6];
    const float* W4  = (const float*)d_in[7];

    float* out_st = (float*)d_out;                       // [8192, 128] = out_s|out_t
    float* S      = out_st + (size_t)2 * GN * DH;        // [4096, 4096]

    float *split, *bufAX, *bufH, *bXs, *bXt, *bQ, *bP;
    cudaGetSymbolAddress((void**)&split, g_split);
    cudaGetSymbolAddress((void**)&bufAX, g_bufAX);
    cudaGetSymbolAddress((void**)&bufH,  g_bufH);
    cudaGetSymbolAddress((void**)&bXs,   g_Xs);
    cudaGetSymbolAddress((void**)&bXt,   g_Xt);
    cudaGetSymbolAddress((void**)&bQ,    g_Q);
    cudaGetSymbolAddress((void**)&bP,    g_P);

    // GCN branches
    gcn_branch(A_s, X_s, W1, W2, bXs, split, bufAX, bufH);
    gcn_branch(A_t, X_t, W1, W2, bXt, split, bufAX, bufH);

    // Q = Xs @ W3
    mma_launch<128, false, 0>(bXs, W3, bQ, GN, DH, DH, DH, DH, DH, 1);

    // S = exp(Q @ Xt^T)  BM=256 -> grid(32,16)=512 CTAs, fast_exp epilogue
    mma_launch<256, true, 2>(bQ, bXt, S, GN, GN, DH, DH, DH, GN, 1);

    // XsXt = [Xs | Xt]  [4096, 256]  (reuse bufAX)
    pack_kernel<<<GN * 256 / (4 * 256), 256>>>(bXs, bXt, bufAX);

    // P_pair = S @ [Xs|Xt]  [4096,256], K=4096, BM=256, split-K=4 (one pass over S)
    mma_launch<256, false, 0>(S, bufAX, split, GN, 2 * DH, GN, GN, 2 * DH, 2 * DH, 4);
    reduce_deint_kernel<<<8192 * 128 / (4 * 256), 256>>>(split, bP, 4);

    // [out_s; out_t] = [Ps; Pt] @ W4   (M = 8192, writes d_out directly)
    mma_launch<128, false, 0>(bP, W4, out_st, 2 * GN, DH, DH, DH, DH, DH, 1);
}